// round 1
// baseline (speedup 1.0000x reference)
#include <cuda_runtime.h>

// SSIM loss, fused single-pass: 16x3x512x512 fp32 pred/target -> scalar.
// Separable 11x11 Gaussian (sigma=1.5) over 5 fields (x, y, x^2, y^2, xy),
// per-pixel SSIM map, global mean, out = 1 - mean.

#define IMG   512
#define NIMG  16
#define CHN   3
#define PLANES (NIMG*CHN)            // 48
#define KW    11
#define KR    5
#define TW    128                    // tile width (cols per block)
#define TH    32                     // tile height (output rows per block)
#define HROWS (TH + 2*KR)            // 42 h-blurred rows needed
#define SW    (TW + 2*KR)            // 138 staged input cols
#define SWP   140                    // padded stage row
#define NTHREADS 128
#define NPIX  ((long long)NIMG*CHN*IMG*IMG)

// Gaussian weights (sigma=1.5, normalized), fp32-accurate literals.
__device__ __constant__ static const float GW_unused = 0.f; // (placeholder, weights are constexpr below)

__device__ double g_sum;

__global__ void ssim_zero_kernel() { g_sum = 0.0; }

__global__ __launch_bounds__(NTHREADS, 2)
void ssim_main_kernel(const float* __restrict__ pred,
                      const float* __restrict__ targ)
{
    constexpr float W[KW] = {
        0.00102838f, 0.00759876f, 0.03600077f, 0.10936069f, 0.21300554f,
        0.26601173f,
        0.21300554f, 0.10936069f, 0.03600077f, 0.00759876f, 0.00102838f
    };
    constexpr float C1 = 0.0001f;   // 0.01^2
    constexpr float C2 = 0.0009f;   // 0.03^2

    extern __shared__ float sm[];
    // layout: stage x [2][SWP], stage y [2][SWP], hbuf [5][HROWS][TW]
    float* sx0 = sm;                      // 2*SWP
    float* sy0 = sm + 2*SWP;              // 2*SWP
    float* hb  = sm + 4*SWP;              // 5*HROWS*TW

    const int t  = threadIdx.x;
    const int x0 = blockIdx.x * TW;
    const int y0 = blockIdx.y * TH;
    const int plane = blockIdx.z;

    const float* __restrict__ xin = pred + (size_t)plane * IMG * IMG;
    const float* __restrict__ yin = targ + (size_t)plane * IMG * IMG;

    // ---------------- Phase A: horizontal blur of 5 fields ----------------
    for (int j = 0; j < HROWS; ++j) {
        const int gy = y0 - KR + j;
        float* sx = sx0 + (j & 1) * SWP;
        float* sy = sy0 + (j & 1) * SWP;

        // stage one input row (with zero padding outside the image)
        const bool rowok = (gy >= 0) && (gy < IMG);
        #pragma unroll
        for (int i = t; i < SW; i += NTHREADS) {
            const int gx = x0 - KR + i;
            const bool ok = rowok && (gx >= 0) && (gx < IMG);
            sx[i] = ok ? xin[gy * IMG + gx] : 0.0f;
            sy[i] = ok ? yin[gy * IMG + gx] : 0.0f;
        }
        __syncthreads();

        float hx = 0.f, hy = 0.f, hxx = 0.f, hyy = 0.f, hxy = 0.f;
        #pragma unroll
        for (int k = 0; k < KW; ++k) {
            const float a  = sx[t + k];
            const float b  = sy[t + k];
            const float ta = W[k] * a;
            const float tb = W[k] * b;
            hx  += ta;
            hy  += tb;
            hxx = fmaf(ta, a, hxx);
            hyy = fmaf(tb, b, hyy);
            hxy = fmaf(ta, b, hxy);
        }
        float* r = hb + j * TW + t;
        r[0*HROWS*TW] = hx;
        r[1*HROWS*TW] = hy;
        r[2*HROWS*TW] = hxx;
        r[3*HROWS*TW] = hyy;
        r[4*HROWS*TW] = hxy;
        // next iteration stages the other buffer; the buffer written two
        // iterations from now is fenced by the intervening __syncthreads().
    }
    __syncthreads();

    // ---------------- Phase B: streaming vertical blur + SSIM --------------
    // Thread t owns column t. 5 fields x 11 pending output rows of
    // register accumulators; each h-blurred value is read from smem once.
    float aX[11], aY[11], aXX[11], aYY[11], aXY[11];
    #pragma unroll
    for (int s = 0; s < 11; ++s) { aX[s]=0.f; aY[s]=0.f; aXX[s]=0.f; aYY[s]=0.f; aXY[s]=0.f; }

    float tsum = 0.f;

    #pragma unroll
    for (int j = 0; j < HROWS; ++j) {
        const float* r = hb + j * TW + t;
        const float v0 = r[0*HROWS*TW];
        const float v1 = r[1*HROWS*TW];
        const float v2 = r[2*HROWS*TW];
        const float v3 = r[3*HROWS*TW];
        const float v4 = r[4*HROWS*TW];

        #pragma unroll
        for (int p = 0; p < KW; ++p) {
            const int o = j - p;           // output row this tap contributes to
            if (o < 0 || o >= TH) continue;
            const int s = o % 11;          // compile-time after full unroll
            aX [s] = fmaf(W[p], v0, aX [s]);
            aY [s] = fmaf(W[p], v1, aY [s]);
            aXX[s] = fmaf(W[p], v2, aXX[s]);
            aYY[s] = fmaf(W[p], v3, aYY[s]);
            aXY[s] = fmaf(W[p], v4, aXY[s]);
        }

        // output row o = j - 10 just received its last tap -> finalize
        const int o = j - (KW - 1);
        if (o >= 0) {
            const int s = o % 11;
            const float mux  = aX[s], muy = aY[s];
            const float mux2 = mux * mux;
            const float muy2 = muy * muy;
            const float muxy = mux * muy;
            const float sgx  = aXX[s] - mux2;
            const float sgy  = aYY[s] - muy2;
            const float sgxy = aXY[s] - muxy;
            const float num  = (2.0f * muxy + C1) * (2.0f * sgxy + C2);
            const float den  = (mux2 + muy2 + C1) * (sgx + sgy + C2);
            tsum += __fdividef(num, den);
            aX[s]=0.f; aY[s]=0.f; aXX[s]=0.f; aYY[s]=0.f; aXY[s]=0.f;
        }
    }

    // ---------------- reduction ----------------
    #pragma unroll
    for (int off = 16; off > 0; off >>= 1)
        tsum += __shfl_down_sync(0xffffffffu, tsum, off);

    __syncthreads();               // done with smem reuse regions
    if ((t & 31) == 0) sm[t >> 5] = tsum;
    __syncthreads();
    if (t == 0) {
        const float bs = sm[0] + sm[1] + sm[2] + sm[3];
        atomicAdd(&g_sum, (double)bs);
    }
}

__global__ void ssim_fin_kernel(float* __restrict__ out) {
    out[0] = (float)(1.0 - g_sum / (double)NPIX);
}

extern "C" void kernel_launch(void* const* d_in, const int* in_sizes, int n_in,
                              void* d_out, int out_size)
{
    const float* pred = (const float*)d_in[0];
    const float* targ = (const float*)d_in[1];
    float* out = (float*)d_out;

    const int smem_bytes = (4 * SWP + 5 * HROWS * TW) * sizeof(float);
    static bool attr_done = false;
    // idempotent; safe (and required) before capture-time launch
    cudaFuncSetAttribute(ssim_main_kernel,
                         cudaFuncAttributeMaxDynamicSharedMemorySize,
                         smem_bytes);
    (void)attr_done;

    ssim_zero_kernel<<<1, 1>>>();
    dim3 grid(IMG / TW, IMG / TH, PLANES);   // 4 x 16 x 48
    ssim_main_kernel<<<grid, NTHREADS, smem_bytes>>>(pred, targ);
    ssim_fin_kernel<<<1, 1>>>(out);
}

// round 2
// speedup vs baseline: 3.9918x; 3.9918x over previous
#include <cuda_runtime.h>

// SSIM loss, fully fused streaming kernel.
// 16x3x512x512 fp32 pred/target -> scalar 1 - mean(ssim_map).
// Separable 11x11 Gaussian (sigma=1.5), 5 fields (x, y, x2, y2, xy).
// One thread = one image column of a 128x64 tile; rows streamed with
// ring accumulators whose indices are compile-time constants.

#define IMG   512
#define PLANES 48
#define KW    11
#define KR    5
#define TW    128
#define TH    64
#define NRB   7                  // 7*11 = 77 rows streamed >= TH+10
#define SW    (TW + 2*KR)        // 138
#define NTHREADS 128
#define GRIDX (IMG/TW)           // 4
#define GRIDY (IMG/TH)           // 8
#define NBLK  (GRIDX*GRIDY*PLANES)  // 1536
#define NPIXD ((double)PLANES * IMG * IMG)

__device__ double       g_sum;   // zero-initialized at module load
__device__ unsigned int g_cnt;   // zero-initialized at module load

__global__ __launch_bounds__(NTHREADS, 4)
void ssim_kernel(const float* __restrict__ pred,
                 const float* __restrict__ targ,
                 float* __restrict__ out)
{
    constexpr float W[KW] = {
        0.00102838f, 0.00759876f, 0.03600077f, 0.10936069f, 0.21300554f,
        0.26601173f,
        0.21300554f, 0.10936069f, 0.03600077f, 0.00759876f, 0.00102838f
    };
    constexpr float C1 = 0.0001f;
    constexpr float C2 = 0.0009f;

    __shared__ float sbx[2][SW];
    __shared__ float sby[2][SW];
    __shared__ float wsum[4];

    const int t  = threadIdx.x;
    const int x0 = blockIdx.x * TW;
    const int y0 = blockIdx.y * TH;
    const float* __restrict__ xin = pred + (size_t)blockIdx.z * IMG * IMG;
    const float* __restrict__ yin = targ + (size_t)blockIdx.z * IMG * IMG;

    const int  gx0 = x0 - KR + t;        // always in-bounds horizontally? no: pad
    const int  gx1 = gx0 + TW;           // only threads t < SW-TW use this
    const bool tail = (t < SW - TW);

    // ---- row loader into registers (zero padding outside image) ----
    auto ldrow = [&](int j, float& ax0, float& ax1, float& ay0, float& ay1) {
        const int  gy   = y0 - KR + j;
        const bool rok  = (gy >= 0) && (gy < IMG);
        const bool ok0  = rok && (gx0 >= 0) && (gx0 < IMG);
        const bool ok1  = rok && tail && (gx1 < IMG);
        const long base = (long)gy * IMG;
        ax0 = ok0 ? xin[base + gx0] : 0.0f;
        ay0 = ok0 ? yin[base + gx0] : 0.0f;
        ax1 = ok1 ? xin[base + gx1] : 0.0f;
        ay1 = ok1 ? yin[base + gx1] : 0.0f;
    };

    // ---- ring accumulators (indices always compile-time constants) ----
    float aX[11], aY[11], aXX[11], aYY[11], aXY[11];
    #pragma unroll
    for (int s = 0; s < 11; ++s) { aX[s]=0.f; aY[s]=0.f; aXX[s]=0.f; aYY[s]=0.f; aXY[s]=0.f; }

    float tsum = 0.0f;

    // preload and stage row 0
    {
        float ax0, ax1, ay0, ay1;
        ldrow(0, ax0, ax1, ay0, ay1);
        sbx[0][t] = ax0;  sby[0][t] = ay0;
        if (tail) { sbx[0][TW + t] = ax1;  sby[0][TW + t] = ay1; }
    }
    __syncthreads();

    for (int jb = 0; jb < NRB; ++jb) {
        #pragma unroll
        for (int u = 0; u < 11; ++u) {
            const int j = jb * 11 + u;

            // prefetch row j+1 into registers (overlaps with compute below)
            float nx0, nx1, ny0, ny1;
            ldrow(j + 1, nx0, nx1, ny0, ny1);

            // horizontal blur of 5 fields from staged row j
            const float* sx = sbx[j & 1];
            const float* sy = sby[j & 1];
            float hx = 0.f, hy = 0.f, hxx = 0.f, hyy = 0.f, hxy = 0.f;
            #pragma unroll
            for (int k = 0; k < KW; ++k) {
                const float a  = sx[t + k];
                const float b  = sy[t + k];
                const float ta = W[k] * a;
                const float tb = W[k] * b;
                hx  += ta;
                hy  += tb;
                hxx = fmaf(ta, a, hxx);
                hyy = fmaf(tb, b, hyy);
                hxy = fmaf(ta, b, hxy);
            }

            // vertical ring update: tap p of row j feeds output o = j-p,
            // slot (u-p) mod 11 — a literal after unrolling.
            #pragma unroll
            for (int p = 0; p < KW; ++p) {
                const int s = (u - p + 11) % 11;
                aX [s] = fmaf(W[p], hx , aX [s]);
                aY [s] = fmaf(W[p], hy , aY [s]);
                aXX[s] = fmaf(W[p], hxx, aXX[s]);
                aYY[s] = fmaf(W[p], hyy, aYY[s]);
                aXY[s] = fmaf(W[p], hxy, aXY[s]);
            }

            // finalize output row o = j-10 (slot (u+1)%11), then reset slot.
            {
                const int so = (u + 1) % 11;
                const int o  = j - (KW - 1);
                if (o >= 0 && o < TH) {
                    const float mux  = aX[so], muy = aY[so];
                    const float mux2 = mux * mux;
                    const float muy2 = muy * muy;
                    const float muxy = mux * muy;
                    const float sgx  = aXX[so] - mux2;
                    const float sgy  = aYY[so] - muy2;
                    const float sgxy = aXY[so] - muxy;
                    const float num  = (2.0f * muxy + C1) * (2.0f * sgxy + C2);
                    const float den  = (mux2 + muy2 + C1) * (sgx + sgy + C2);
                    tsum += __fdividef(num, den);
                }
                aX[so]=0.f; aY[so]=0.f; aXX[so]=0.f; aYY[so]=0.f; aXY[so]=0.f;
            }

            // stage prefetched row j+1 into the other buffer.
            // Safe without a pre-store barrier: it overwrites data last read
            // in iteration j-1, which everyone left at that iteration's
            // barrier; current compute reads the other buffer.
            const int nb = (j + 1) & 1;
            sbx[nb][t] = nx0;  sby[nb][t] = ny0;
            if (tail) { sbx[nb][TW + t] = nx1;  sby[nb][TW + t] = ny1; }
            __syncthreads();
        }
    }

    // ---- reduction: warp -> block -> global ----
    #pragma unroll
    for (int off = 16; off > 0; off >>= 1)
        tsum += __shfl_down_sync(0xffffffffu, tsum, off);
    if ((t & 31) == 0) wsum[t >> 5] = tsum;
    __syncthreads();

    if (t == 0) {
        const double bs = (double)wsum[0] + (double)wsum[1]
                        + (double)wsum[2] + (double)wsum[3];
        atomicAdd(&g_sum, bs);
        __threadfence();
        const unsigned r = atomicAdd(&g_cnt, 1u);
        if (r == NBLK - 1u) {
            // all other blocks' g_sum adds are visible (fence before their inc)
            const double s = g_sum;
            out[0] = (float)(1.0 - s / NPIXD);
            g_sum = 0.0;        // reset for next graph replay
            __threadfence();
            g_cnt = 0u;
        }
    }
}

extern "C" void kernel_launch(void* const* d_in, const int* in_sizes, int n_in,
                              void* d_out, int out_size)
{
    const float* pred = (const float*)d_in[0];
    const float* targ = (const float*)d_in[1];
    float* out = (float*)d_out;

    dim3 grid(GRIDX, GRIDY, PLANES);   // 4 x 8 x 48 = 1536 blocks
    ssim_kernel<<<grid, NTHREADS>>>(pred, targ, out);
}

// round 3
// speedup vs baseline: 4.3460x; 1.0887x over previous
#include <cuda_runtime.h>

// SSIM loss, fused streaming kernel with packed f32x2 math (sm_103a FFMA2).
// 16x3x512x512 fp32 pred/target -> scalar 1 - mean(ssim_map).
// x/y interleaved in smem -> each 11-tap read is one LDS.64 pair.
// Fields packed as (mu_x,mu_y) and (E[x^2],E[y^2]); E[xy] scalar.

#define IMG   512
#define PLANES 48
#define KW    11
#define KR    5
#define TW    128
#define TH    64
#define NRB   7                  // 7*11 = 77 rows streamed >= TH+10
#define SW    (TW + 2*KR)        // 138
#define NTHREADS 128
#define GRIDX (IMG/TW)           // 4
#define GRIDY (IMG/TH)           // 8
#define NBLK  (GRIDX*GRIDY*PLANES)  // 1536
#define NPIXD ((double)PLANES * IMG * IMG)

typedef unsigned long long u64;

__device__ double       g_sum;
__device__ unsigned int g_cnt;

// ---- packed f32x2 helpers (Blackwell) ----
__device__ __forceinline__ u64 pk2(float x, float y) {
    u64 r; asm("mov.b64 %0, {%1, %2};" : "=l"(r) : "f"(x), "f"(y)); return r;
}
__device__ __forceinline__ void upk2(u64 v, float& x, float& y) {
    asm("mov.b64 {%0, %1}, %2;" : "=f"(x), "=f"(y) : "l"(v));
}
__device__ __forceinline__ u64 fma2(u64 a, u64 b, u64 c) {
    u64 d; asm("fma.rn.f32x2 %0, %1, %2, %3;" : "=l"(d) : "l"(a), "l"(b), "l"(c));
    return d;
}
__device__ __forceinline__ u64 mul2(u64 a, u64 b) {
    u64 d; asm("mul.rn.f32x2 %0, %1, %2;" : "=l"(d) : "l"(a), "l"(b));
    return d;
}

__global__ __launch_bounds__(NTHREADS, 4)
void ssim_kernel(const float* __restrict__ pred,
                 const float* __restrict__ targ,
                 float* __restrict__ out)
{
    constexpr float W[KW] = {
        0.00102838f, 0.00759876f, 0.03600077f, 0.10936069f, 0.21300554f,
        0.26601173f,
        0.21300554f, 0.10936069f, 0.03600077f, 0.00759876f, 0.00102838f
    };
    constexpr float C1 = 0.0001f;
    constexpr float C2 = 0.0009f;

    __shared__ float2 sb[2][SW];      // interleaved (x, y) staging rows
    __shared__ float  wsum[4];

    const int t  = threadIdx.x;
    const int x0 = blockIdx.x * TW;
    const int y0 = blockIdx.y * TH;
    const float* __restrict__ xin = pred + (size_t)blockIdx.z * IMG * IMG;
    const float* __restrict__ yin = targ + (size_t)blockIdx.z * IMG * IMG;

    const int  gx0  = x0 - KR + t;
    const int  gx1  = gx0 + TW;
    const bool tail = (t < SW - TW);

    auto ldrow = [&](int j, float& ax0, float& ax1, float& ay0, float& ay1) {
        const int  gy  = y0 - KR + j;
        const bool rok = (gy >= 0) && (gy < IMG);
        const bool ok0 = rok && (gx0 >= 0) && (gx0 < IMG);
        const bool ok1 = rok && tail && (gx1 < IMG);
        const long base = (long)gy * IMG;
        ax0 = ok0 ? xin[base + gx0] : 0.0f;
        ay0 = ok0 ? yin[base + gx0] : 0.0f;
        ax1 = ok1 ? xin[base + gx1] : 0.0f;
        ay1 = ok1 ? yin[base + gx1] : 0.0f;
    };

    // packed (W[k], W[k]) weights — held in registers
    u64 WW[KW];
    #pragma unroll
    for (int k = 0; k < KW; ++k) WW[k] = pk2(W[k], W[k]);
    const u64 NEG1 = pk2(-1.0f, -1.0f);
    const u64 Z64  = 0ull;

    // ring accumulators: packed (mu_x,mu_y), packed (sxx,syy), scalar sxy
    u64 aMU[11], aSQ[11];
    float aXY[11];
    #pragma unroll
    for (int s = 0; s < 11; ++s) { aMU[s] = Z64; aSQ[s] = Z64; aXY[s] = 0.f; }

    float tsum = 0.0f;

    // preload + stage row 0
    {
        float ax0, ax1, ay0, ay1;
        ldrow(0, ax0, ax1, ay0, ay1);
        sb[0][t] = make_float2(ax0, ay0);
        if (tail) sb[0][TW + t] = make_float2(ax1, ay1);
    }
    __syncthreads();

    for (int jb = 0; jb < NRB; ++jb) {
        #pragma unroll
        for (int u = 0; u < 11; ++u) {
            const int j = jb * 11 + u;

            // prefetch next row (overlaps compute)
            float nx0, nx1, ny0, ny1;
            ldrow(j + 1, nx0, nx1, ny0, ny1);

            // ---- horizontal blur, packed ----
            const u64* s = (const u64*)sb[j & 1];
            u64 hmu = Z64, hsq = Z64;
            float hxy = 0.f;
            #pragma unroll
            for (int k = 0; k < KW; ++k) {
                const u64 p  = s[t + k];          // (a, b) LDS.64
                const u64 pp = mul2(p, p);        // (a^2, b^2)
                hmu = fma2(WW[k], p,  hmu);
                hsq = fma2(WW[k], pp, hsq);
                float a, b; upk2(p, a, b);
                hxy = fmaf(W[k], a * b, hxy);
            }

            // ---- vertical ring update (slot indices are literals) ----
            #pragma unroll
            for (int p = 0; p < KW; ++p) {
                const int ss = (u - p + 11) % 11;
                aMU[ss] = fma2(WW[p], hmu, aMU[ss]);
                aSQ[ss] = fma2(WW[p], hsq, aSQ[ss]);
                aXY[ss] = fmaf(W[p], hxy, aXY[ss]);
            }

            // ---- finalize output row o = j-10, then reset its slot ----
            {
                const int so = (u + 1) % 11;
                const int o  = j - (KW - 1);
                if (o >= 0 && o < TH) {
                    const u64 mu  = aMU[so];
                    const u64 mu2 = mul2(mu, mu);           // (mux^2, muy^2)
                    const u64 sg  = fma2(mu2, NEG1, aSQ[so]); // (sgx, sgy)
                    float mux, muy, m2x, m2y, sgx, sgy;
                    upk2(mu,  mux, muy);
                    upk2(mu2, m2x, m2y);
                    upk2(sg,  sgx, sgy);
                    const float muxy = mux * muy;
                    const float sgxy = aXY[so] - muxy;
                    const float num  = (2.0f * muxy + C1) * (2.0f * sgxy + C2);
                    const float den  = (m2x + m2y + C1) * (sgx + sgy + C2);
                    tsum += __fdividef(num, den);
                }
                aMU[so] = Z64; aSQ[so] = Z64; aXY[so] = 0.f;
            }

            // stage prefetched row into the other buffer (see barrier note:
            // overwrites data last read before the previous barrier)
            const int nb = (j + 1) & 1;
            sb[nb][t] = make_float2(nx0, ny0);
            if (tail) sb[nb][TW + t] = make_float2(nx1, ny1);
            __syncthreads();
        }
    }

    // ---- reduction: warp -> block -> global ----
    #pragma unroll
    for (int off = 16; off > 0; off >>= 1)
        tsum += __shfl_down_sync(0xffffffffu, tsum, off);
    if ((t & 31) == 0) wsum[t >> 5] = tsum;
    __syncthreads();

    if (t == 0) {
        const double bs = (double)wsum[0] + (double)wsum[1]
                        + (double)wsum[2] + (double)wsum[3];
        atomicAdd(&g_sum, bs);
        __threadfence();
        const unsigned r = atomicAdd(&g_cnt, 1u);
        if (r == NBLK - 1u) {
            const double sall = g_sum;
            out[0] = (float)(1.0 - sall / NPIXD);
            g_sum = 0.0;
            __threadfence();
            g_cnt = 0u;
        }
    }
}

extern "C" void kernel_launch(void* const* d_in, const int* in_sizes, int n_in,
                              void* d_out, int out_size)
{
    const float* pred = (const float*)d_in[0];
    const float* targ = (const float*)d_in[1];
    float* out = (float*)d_out;

    dim3 grid(GRIDX, GRIDY, PLANES);   // 4 x 8 x 48 = 1536 blocks
    ssim_kernel<<<grid, NTHREADS>>>(pred, targ, out);
}